// round 5
// baseline (speedup 1.0000x reference)
#include <cuda_runtime.h>
#include <cuda_bf16.h>
#include <math.h>

// Problem constants (fixed by the reference)
#define BB 4
#define TT 512
#define TP 1024
#define CC 32
#define KK 128
#define NW 16                 // 32-bit words per 512-event mask
#define EPSF 2.220446049250313e-16f

// ---------------- device scratch (no allocations allowed) ----------------
__device__ float g_NPD[CC * CC];                 // -(softplus(delta)+EPS)
__device__ float g_spmu[CC];                     // softplus(mu)
__device__ float g_pfine[KK];                    // fine probs
__device__ int   g_gbase[BB * CC];               // per-(b,e) start row in GP table
__device__ unsigned g_mask [BB * (NW + 1) * CC]; // [b][w][e] event bitmask (word 16 = 0 pad)
__device__ int      g_wpref[BB * (NW + 1) * CC]; // [b][w][e] counts below word w (word 16 = n)
__device__ float g_GP[BB * (TT + CC) * CC];      // GP rows: pa[e][c] * prefix-sum of exp(pd*pt)

__device__ __forceinline__ float softplusf(float x) {
    return log1pf(expf(x));
}

// ---------------- kernel A: everything up front, one block ----------------
__global__ __launch_bounds__(256) void setup_kernel(
    const int*   __restrict__ past_event,   // [B,T]
    const float* __restrict__ past_time,    // [B,T]
    const float* __restrict__ mu,           // [C]
    const float* __restrict__ alpha,        // [C,C]
    const float* __restrict__ delta,        // [C,C]
    const float* __restrict__ cf,           // [K]
    const int*   __restrict__ ftc)          // [K]
{
    __shared__ int      sh_ev[BB * TT];               // 8 KB
    __shared__ float    sh_gtg[BB * TT];              // 8 KB (times grouped by type)
    __shared__ unsigned sh_mask [BB * (NW + 1) * CC]; // 8.7 KB
    __shared__ int      sh_wpref[BB * (NW + 1) * CC]; // 8.7 KB
    __shared__ float    sh_PA[CC * CC];               // 4 KB softplus(alpha)[e][c]
    __shared__ float    sh_PD[CC * CC];               // 4 KB softplus(delta)[e][c]+EPS
    __shared__ float    sh_e[KK];
    __shared__ int      sh_ftc[KK];
    __shared__ float    sh_den[CC];
    __shared__ int      sh_obase[BB * CC];
    __shared__ int      sh_gb[BB * CC];
    __shared__ int      sh_ob[BB * CC];   // per-group start slot (copy for prefix phase)
    __shared__ float    sh_max;

    const int tid  = threadIdx.x;
    const int lane = tid & 31;
    const int wrp  = tid >> 5;

    // Phase 1: softplus tables, mu, load events/logits
    for (int i = tid; i < CC * CC; i += 256) {
        sh_PA[i] = softplusf(alpha[i]);
        float pd = softplusf(delta[i]) + EPSF;
        sh_PD[i] = pd;
        g_NPD[i] = -pd;
    }
    if (tid < CC) g_spmu[tid] = softplusf(mu[tid]);
    for (int i = tid; i < BB * TT; i += 256) sh_ev[i] = past_event[i];
    if (tid < KK) sh_ftc[tid] = ftc[tid];
    if (tid == 0) {
        float m = cf[0];
        for (int k = 1; k < KK; k++) m = fmaxf(m, cf[k]);
        sh_max = m;
    }
    __syncthreads();

    // Phase 2: event bitmasks via ballot. 64 windows (b,w), 8 warps -> 8 rounds.
    if (tid < KK) sh_e[tid] = expf(cf[tid] - sh_max);
    for (int r = 0; r < 8; r++) {
        int widx = wrp + 8 * r;            // 0..63
        int b = widx >> 4, w = widx & 15;
        int ev = sh_ev[b * TT + w * 32 + lane];
        unsigned mym = 0u;
#pragma unroll
        for (int e = 0; e < CC; e++) {
            unsigned m = __ballot_sync(0xffffffffu, ev == e);
            if (lane == e) mym = m;
        }
        sh_mask[(b * (NW + 1) + w) * CC + lane] = mym;
    }
    __syncthreads();

    // Phase 3: word-prefix counts per (b,e); pad word 16 (wpref=n, mask=0)
    if (tid < BB * CC) {
        const int b = tid >> 5, e = tid & 31;
        int base = b * (NW + 1) * CC + e;
        int c = 0;
#pragma unroll
        for (int w = 0; w < NW; w++) {
            sh_wpref[base + w * CC] = c;
            c += __popc(sh_mask[base + w * CC]);
        }
        sh_wpref[base + NW * CC] = c;      // total n
        sh_mask [base + NW * CC] = 0u;
    }
    __syncthreads();

    // Phase 4: segment denominators; per-batch group bases
    if (tid < CC) {
        float d = 0.f;
        for (int k = 0; k < KK; k++)
            if (sh_ftc[k] == tid) d += sh_e[k];
        sh_den[tid] = d;
    }
    if (tid < BB) {
        const int b = tid;
        int ob = 0, gb = b * (TT + CC);
        for (int e = 0; e < CC; e++) {
            int n = sh_wpref[(b * (NW + 1) + NW) * CC + e];
            sh_obase[b * CC + e] = ob;
            sh_ob[b * CC + e] = ob;
            sh_gb[b * CC + e] = gb;
            g_gbase[b * CC + e] = gb;
            ob += n;
            gb += n + 1;
        }
    }
    __syncthreads();

    // Phase 5: fine probs; scatter times into grouped order (popc addressing);
    //          export masks/prefixes for the main kernel
    if (tid < KK) g_pfine[tid] = sh_e[tid] / sh_den[sh_ftc[tid]];
    for (int i = tid; i < BB * TT; i += 256) {
        int b = i >> 9, t = i & (TT - 1);
        int e = sh_ev[i];
        int w = t >> 5, r = t & 31;
        int base = (b * (NW + 1) + w) * CC + e;
        int j = sh_wpref[base] + __popc(sh_mask[base] & ((1u << r) - 1u));
        sh_gtg[b * TT + sh_obase[b * CC + e] + j] = past_time[i];
    }
    for (int i = tid; i < BB * (NW + 1) * CC; i += 256) {
        g_mask[i]  = sh_mask[i];
        g_wpref[i] = sh_wpref[i];
    }
    __syncthreads();

    // Phase 6 (merged prefix kernel): per (b,e) group, lane = c.
    // GP[row j] = pa[e][c] * sum_{j'<j} exp(pd[e][c] * pt_{j'})
    for (int r = 0; r < BB * CC / 8; r++) {
        int g = wrp + 8 * r;               // 0..127 -> (b,e)
        int b = g >> 5, e = g & 31;
        const float pd = sh_PD[e * CC + lane];
        const float pa = sh_PA[e * CC + lane];
        const int n  = sh_wpref[(b * (NW + 1) + NW) * CC + e];
        const int ob = sh_ob[b * CC + e];
        const int base = sh_gb[b * CC + e] * CC;
        g_GP[base + lane] = 0.f;
        float s = 0.f;
        for (int j = 0; j < n; j++) {
            float pt = sh_gtg[b * TT + ob + j];
            s += __expf(pd * pt);
            g_GP[base + (j + 1) * CC + lane] = s * pa;
        }
    }
}

// ---------------- kernel C: main evaluation. warp per (b,tp), lane = c ----------------
__global__ __launch_bounds__(256) void main_kernel(
    const float* __restrict__ past_time,    // [B,T]
    const float* __restrict__ time_tensor,  // [B,TP]
    const int*   __restrict__ ftc,          // [K]
    float*       __restrict__ out)          // [B,TP,K]
{
    __shared__ float    sh_npd[CC * CC];           // 4 KB
    __shared__ float    sh_t[TT];                  // 2 KB (batch's sorted event times)
    __shared__ unsigned sh_mask [(NW + 1) * CC];   // 2.2 KB
    __shared__ int      sh_wpref[(NW + 1) * CC];   // 2.2 KB
    __shared__ int      sh_gbase[CC];
    __shared__ float    sh_spmu[CC];
    __shared__ float    sh_pf[KK];
    __shared__ int      sh_ftc[KK];
    __shared__ float    sh_acc[8][CC];

    const int b = blockIdx.y;
    const int tid = threadIdx.x;
    for (int i = tid; i < CC * CC; i += 256) sh_npd[i] = g_NPD[i];
    for (int i = tid; i < TT; i += 256)      sh_t[i] = past_time[b * TT + i];
    for (int i = tid; i < (NW + 1) * CC; i += 256) {
        sh_mask[i]  = g_mask [b * (NW + 1) * CC + i];
        sh_wpref[i] = g_wpref[b * (NW + 1) * CC + i];
    }
    if (tid < CC) { sh_gbase[tid] = g_gbase[b * CC + tid]; sh_spmu[tid] = g_spmu[tid]; }
    if (tid < KK) { sh_pf[tid] = g_pfine[tid]; sh_ftc[tid] = ftc[tid]; }
    __syncthreads();

    const int w = tid >> 5, lane = tid & 31;
    const int tp = blockIdx.x * 8 + w;
    const float tt = time_tensor[b * TP + tp];

    // warp-uniform binary search: J = #events with (tt - pt) > EPS (monotone in t)
    int lo = 0, hi = TT;
    while (lo < hi) {
        int mid = (lo + hi) >> 1;
        if (tt - sh_t[mid] > EPSF) lo = mid + 1; else hi = mid;
    }
    const int J = lo;

    // lane l resolves GP row for event-type e = l via bitmask popcount
    const int wd = J >> 5, rb = J & 31;
    const int jl = sh_wpref[wd * CC + lane]
                 + __popc(sh_mask[wd * CC + lane] & ((1u << rb) - 1u));
    const int rowl = sh_gbase[lane] + jl;

    float acc = 0.f;
#pragma unroll
    for (int e = 0; e < CC; e++) {
        int row = __shfl_sync(0xffffffffu, rowl, e);
        float gp = g_GP[row * CC + lane];              // coalesced 128B, L2 resident
        float ex = __expf(sh_npd[e * CC + lane] * tt); // MUFU
        acc = fmaf(ex, gp, acc);
    }

    sh_acc[w][lane] = acc;
    __syncwarp();
    float* o = out + (b * TP + tp) * KK;
#pragma unroll
    for (int i = 0; i < 4; i++) {
        int k = lane + 32 * i;
        int c = sh_ftc[k];
        o[k] = (sh_acc[w][c] + sh_spmu[c]) * sh_pf[k];
    }
}

// ---------------- launch ----------------
extern "C" void kernel_launch(void* const* d_in, const int* in_sizes, int n_in,
                              void* d_out, int out_size)
{
    const int*   past_event  = (const int*)  d_in[0];
    const float* past_time   = (const float*)d_in[1];
    const float* time_tensor = (const float*)d_in[2];
    const float* mu          = (const float*)d_in[3];
    const float* alpha       = (const float*)d_in[4];
    const float* delta       = (const float*)d_in[5];
    const float* cf_logits   = (const float*)d_in[6];
    const int*   ftc         = (const int*)  d_in[7];
    float* out = (float*)d_out;

    setup_kernel<<<1, 256>>>(past_event, past_time, mu, alpha, delta, cf_logits, ftc);
    main_kernel<<<dim3(TP / 8, BB), 256>>>(past_time, time_tensor, ftc, out);
}

// round 8
// speedup vs baseline: 1.2545x; 1.2545x over previous
#include <cuda_runtime.h>
#include <cuda_bf16.h>
#include <math.h>

// Problem constants (fixed by the reference)
#define BB 4
#define TT 512
#define TP 1024
#define CC 32
#define KK 128
#define NW 16                 // 32-bit words per 512-event mask
#define EPSF 2.220446049250313e-16f

// ---------------- device scratch (no allocations allowed) ----------------
__device__ float g_PA[CC * CC];                  // softplus(alpha)[e][c]
__device__ float g_PD[CC * CC];                  // softplus(delta)[e][c]+EPS
__device__ float g_NPD[CC * CC];                 // -(softplus(delta)+EPS)
__device__ float g_spmu[CC];                     // softplus(mu)
__device__ float g_pfine[KK];                    // fine probs
__device__ int   g_obase[BB * CC];               // per-(b,e) start slot in grouped list
__device__ int   g_gbase[BB * CC];               // per-(b,e) start row in GP table
__device__ int   g_n[BB * CC];                   // group sizes
__device__ float g_gtg[BB * TT];                 // times grouped by event type
__device__ unsigned g_mask [BB * (NW + 1) * CC]; // [b][w][e] event bitmask (word 16 = 0)
__device__ int      g_wpref[BB * (NW + 1) * CC]; // [b][w][e] count below word w (word 16 = n)
__device__ float g_GP[BB * (TT + CC) * CC];      // GP rows: pa[e][c]*prefix-sum exp(pd*pt)

__device__ __forceinline__ float softplusf(float x) {
    return log1pf(expf(x));
}

// ---------------- kernel A: one block per batch; block 0 also does tables ----------------
__global__ __launch_bounds__(256) void setup_kernel(
    const int*   __restrict__ past_event,   // [B,T]
    const float* __restrict__ past_time,    // [B,T]
    const float* __restrict__ mu,           // [C]
    const float* __restrict__ alpha,        // [C,C]
    const float* __restrict__ delta,        // [C,C]
    const float* __restrict__ cf,           // [K]
    const int*   __restrict__ ftc)          // [K]
{
    __shared__ int      sh_ev[TT];                // 2 KB
    __shared__ unsigned sh_mask [(NW + 1) * CC];  // 2.2 KB
    __shared__ int      sh_wpref[(NW + 1) * CC];  // 2.2 KB
    __shared__ int      sh_obase[CC];
    __shared__ float    sh_ex[KK];
    __shared__ float    sh_den[CC];
    __shared__ float    sh_max;

    const int b    = blockIdx.x;
    const int tid  = threadIdx.x;
    const int lane = tid & 31;
    const int wrp  = tid >> 5;

    for (int i = tid; i < TT; i += 256) sh_ev[i] = past_event[b * TT + i];
    __syncthreads();

    // bitmasks via ballot: 16 windows, 8 warps -> 2 rounds
    for (int r = 0; r < 2; r++) {
        int w = wrp + 8 * r;
        int ev = sh_ev[w * 32 + lane];
        unsigned mym = 0u;
#pragma unroll
        for (int e = 0; e < CC; e++) {
            unsigned m = __ballot_sync(0xffffffffu, ev == e);
            if (lane == e) mym = m;
        }
        sh_mask[w * CC + lane] = mym;
    }
    __syncthreads();

    // word-prefix counts per e (16-step popc chain, one thread per e)
    if (tid < CC) {
        int c = 0;
#pragma unroll
        for (int w = 0; w < NW; w++) {
            sh_wpref[w * CC + tid] = c;
            c += __popc(sh_mask[w * CC + tid]);
        }
        sh_wpref[NW * CC + tid] = c;   // total n
        sh_mask [NW * CC + tid] = 0u;  // pad word for J=512
    }
    __syncthreads();

    // group bases (trivial 32-iter serial, one thread)
    if (tid == 0) {
        int ob = 0, gb = b * (TT + CC);
        for (int e = 0; e < CC; e++) {
            int n = sh_wpref[NW * CC + e];
            sh_obase[e] = ob;
            g_obase[b * CC + e] = ob;
            g_gbase[b * CC + e] = gb;
            g_n[b * CC + e] = n;
            ob += n;
            gb += n + 1;
        }
    }
    __syncthreads();

    // scatter times into grouped order (popc addressing); export masks/prefixes
    for (int t = tid; t < TT; t += 256) {
        int e = sh_ev[t];
        int w = t >> 5, rb = t & 31;
        int j = sh_wpref[w * CC + e] + __popc(sh_mask[w * CC + e] & ((1u << rb) - 1u));
        g_gtg[b * TT + sh_obase[e] + j] = past_time[b * TT + t];
    }
    for (int i = tid; i < (NW + 1) * CC; i += 256) {
        g_mask [b * (NW + 1) * CC + i] = sh_mask[i];
        g_wpref[b * (NW + 1) * CC + i] = sh_wpref[i];
    }

    // block 0: softplus tables + fine probs (runs in parallel with blocks 1..3)
    if (b == 0) {
        for (int i = tid; i < CC * CC; i += 256) {
            g_PA[i] = softplusf(alpha[i]);
            float pd = softplusf(delta[i]) + EPSF;
            g_PD[i] = pd;
            g_NPD[i] = -pd;
        }
        if (tid < CC) g_spmu[tid] = softplusf(mu[tid]);
        if (tid < KK) sh_ex[tid] = cf[tid];
        __syncthreads();
        if (tid < 32) {
            float m = fmaxf(fmaxf(sh_ex[tid], sh_ex[tid + 32]),
                            fmaxf(sh_ex[tid + 64], sh_ex[tid + 96]));
#pragma unroll
            for (int d = 16; d >= 1; d >>= 1)
                m = fmaxf(m, __shfl_xor_sync(0xffffffffu, m, d));
            if (tid == 0) sh_max = m;
        }
        __syncthreads();
        float ex = 0.f;
        if (tid < KK) { ex = expf(sh_ex[tid] - sh_max); sh_ex[tid] = ex; }
        __syncthreads();
        if (tid < CC) {
            float d = 0.f;
            for (int k = 0; k < KK; k++)
                if (ftc[k] == tid) d += sh_ex[k];
            sh_den[tid] = d;
        }
        __syncthreads();
        if (tid < KK) g_pfine[tid] = ex / sh_den[ftc[tid]];
    }
}

// ---------------- kernel B: per-(b,e) GP prefix, 128 blocks, pipelined exp ----------------
__global__ __launch_bounds__(32) void prefix_kernel()
{
    __shared__ float st[TT];
    const int g = blockIdx.x;            // 0..127 -> (b,e)
    const int b = g >> 5, e = g & 31;
    const int lane = threadIdx.x;        // = c
    const float pd = g_PD[e * CC + lane];
    const float pa = g_PA[e * CC + lane];
    const int n    = g_n[b * CC + e];
    const int ob   = g_obase[b * CC + e];
    const int base = g_gbase[b * CC + e] * CC;

    for (int i = lane; i < n; i += 32) st[i] = g_gtg[b * TT + ob + i];
    __syncwarp();

    g_GP[base + lane] = 0.f;             // j = 0 row
    float s = 0.f;
    int j = 0;
    for (; j + 4 <= n; j += 4) {         // exps independent: pipeline 4 ahead of FADD chain
        float x0 = __expf(pd * st[j]);
        float x1 = __expf(pd * st[j + 1]);
        float x2 = __expf(pd * st[j + 2]);
        float x3 = __expf(pd * st[j + 3]);
        s += x0; g_GP[base + (j + 1) * CC + lane] = s * pa;
        s += x1; g_GP[base + (j + 2) * CC + lane] = s * pa;
        s += x2; g_GP[base + (j + 3) * CC + lane] = s * pa;
        s += x3; g_GP[base + (j + 4) * CC + lane] = s * pa;
    }
    for (; j < n; j++) {
        s += __expf(pd * st[j]);
        g_GP[base + (j + 1) * CC + lane] = s * pa;
    }
}

// ---------------- kernel C: warp handles 4 tp's (ILP), 128 blocks ----------------
__global__ __launch_bounds__(256, 1) void main_kernel(
    const float* __restrict__ past_time,    // [B,T]
    const float* __restrict__ time_tensor,  // [B,TP]
    const int*   __restrict__ ftc,          // [K]
    float*       __restrict__ out)          // [B,TP,K]
{
    __shared__ float    sh_npd[CC * CC];           // 4 KB
    __shared__ float    sh_t[TT];                  // 2 KB
    __shared__ unsigned sh_mask [(NW + 1) * CC];   // 2.2 KB
    __shared__ int      sh_wpref[(NW + 1) * CC];   // 2.2 KB
    __shared__ int      sh_gbase[CC];

    const int b   = blockIdx.y;
    const int tid = threadIdx.x;
    const int w   = tid >> 5, lane = tid & 31;

    for (int i = tid; i < CC * CC; i += 256) sh_npd[i] = g_NPD[i];
    for (int i = tid; i < TT; i += 256)      sh_t[i] = past_time[b * TT + i];
    for (int i = tid; i < (NW + 1) * CC; i += 256) {
        sh_mask[i]  = g_mask [b * (NW + 1) * CC + i];
        sh_wpref[i] = g_wpref[b * (NW + 1) * CC + i];
    }
    if (tid < CC) sh_gbase[tid] = g_gbase[b * CC + tid];

    // per-lane epilogue tables (from global; no block sync needed)
    int ck[4]; float pf[4], sm[4];
#pragma unroll
    for (int j = 0; j < 4; j++) {
        int k = lane + 32 * j;
        ck[j] = ftc[k];
        pf[j] = g_pfine[k];
        sm[j] = g_spmu[ck[j]];
    }
    __syncthreads();

    const int tp0 = (blockIdx.x * 8 + w) * 4;
    float tt[4];
#pragma unroll
    for (int i = 0; i < 4; i++) tt[i] = time_tensor[b * TP + tp0 + i];

    // branchless binary count: J = #events with (tt - pt) > EPS, 4 interleaved chains
    int pos[4] = {0, 0, 0, 0};
#pragma unroll
    for (int s = 512; s >= 1; s >>= 1) {
#pragma unroll
        for (int i = 0; i < 4; i++) {
            int cand = pos[i] + s;
            if (cand <= TT && (tt[i] - sh_t[cand - 1] > EPSF)) pos[i] = cand;
        }
    }

    // lane l resolves GP row for event-type e = l via bitmask popcount
    int rowl[4];
#pragma unroll
    for (int i = 0; i < 4; i++) {
        int J = pos[i], wd = J >> 5, rb = J & 31;
        int jl = sh_wpref[wd * CC + lane]
               + __popc(sh_mask[wd * CC + lane] & ((1u << rb) - 1u));
        rowl[i] = sh_gbase[lane] + jl;
    }

    float acc[4] = {0.f, 0.f, 0.f, 0.f};
#pragma unroll
    for (int e = 0; e < CC; e++) {
        float npd = sh_npd[e * CC + lane];
#pragma unroll
        for (int i = 0; i < 4; i++) {
            int r = __shfl_sync(0xffffffffu, rowl[i], e);
            float gp = g_GP[r * CC + lane];               // coalesced 128B, L2 resident
            acc[i] = fmaf(__expf(npd * tt[i]), gp, acc[i]);
        }
    }

    // epilogue: out[k] = (acc[ftc[k]] + spmu) * pfine[k], via shfl (no shared round-trip)
#pragma unroll
    for (int i = 0; i < 4; i++) {
        float* o = out + (b * TP + tp0 + i) * KK;
#pragma unroll
        for (int j = 0; j < 4; j++) {
            float v = __shfl_sync(0xffffffffu, acc[i], ck[j]);
            o[lane + 32 * j] = (v + sm[j]) * pf[j];
        }
    }
}

// ---------------- launch ----------------
extern "C" void kernel_launch(void* const* d_in, const int* in_sizes, int n_in,
                              void* d_out, int out_size)
{
    const int*   past_event  = (const int*)  d_in[0];
    const float* past_time   = (const float*)d_in[1];
    const float* time_tensor = (const float*)d_in[2];
    const float* mu          = (const float*)d_in[3];
    const float* alpha       = (const float*)d_in[4];
    const float* delta       = (const float*)d_in[5];
    const float* cf_logits   = (const float*)d_in[6];
    const int*   ftc         = (const int*)  d_in[7];
    float* out = (float*)d_out;

    setup_kernel<<<BB, 256>>>(past_event, past_time, mu, alpha, delta, cf_logits, ftc);
    prefix_kernel<<<BB * CC, 32>>>();
    main_kernel<<<dim3(TP / 32, BB), 256>>>(past_time, time_tensor, ftc, out);
}

// round 9
// speedup vs baseline: 2.2743x; 1.8130x over previous
#include <cuda_runtime.h>
#include <cuda_bf16.h>
#include <math.h>

// Problem constants (fixed by the reference)
#define BB 4
#define TT 512
#define TP 1024
#define CC 32
#define KK 128
#define NW 16                 // 32-bit words per 512-event mask
#define GPROWS (TT + CC)      // 544 GP rows per batch
#define EPSF 2.220446049250313e-16f

struct Smem {
    float    gp[GPROWS * CC];        // 68 KB: pa[e][c]*prefix-sum exp(pd*pt)
    float    pd[CC * CC];            // softplus(delta)[e][c]+EPS
    float    pa[CC * CC];            // softplus(alpha)[e][c]
    float    t[TT];                  // batch's sorted event times
    float    gtg[TT];                // times grouped by event type
    int      ev[TT];                 // event ids
    unsigned mask[(NW + 1) * CC];    // [w][e] bitmask (word 16 = 0 pad)
    int      wpref[(NW + 1) * CC];   // [w][e] count below word w (word 16 = n)
    int      obase[CC];              // group start in gtg
    int      gbase[CC];              // group start row in gp
    int      gn[CC];                 // group sizes
    float    ex[KK];                 // cf logits -> exp(cf - max)
    int      ftc_s[KK];
    float    part[4 * CC];           // den partials (quarters, fixed order)
    float    pf[KK];                 // fine probs
    float    spmu[CC];               // softplus(mu)
};

__device__ __forceinline__ float softplusf(float x) {
    return log1pf(expf(x));
}

extern __shared__ char smem_raw[];

// One fused kernel: block = (tp-chunk, batch). Each block rebuilds its batch's
// setup in shared (redundant, parallel), then evaluates 32 tp's (4 per warp).
__global__ __launch_bounds__(256, 1) void fused_kernel(
    const int*   __restrict__ past_event,   // [B,T]
    const float* __restrict__ past_time,    // [B,T]
    const float* __restrict__ time_tensor,  // [B,TP]
    const float* __restrict__ mu,           // [C]
    const float* __restrict__ alpha,        // [C,C]
    const float* __restrict__ delta,        // [C,C]
    const float* __restrict__ cf,           // [K]
    const int*   __restrict__ ftc,          // [K]
    float*       __restrict__ out)          // [B,TP,K]
{
    Smem* s = reinterpret_cast<Smem*>(smem_raw);
    const int b    = blockIdx.y;
    const int tid  = threadIdx.x;
    const int lane = tid & 31;
    const int wrp  = tid >> 5;

    // ---- phase 1: global loads + softplus tables ----
    for (int i = tid; i < TT; i += 256) {
        s->ev[i] = past_event[b * TT + i];
        s->t[i]  = past_time [b * TT + i];
    }
    for (int i = tid; i < CC * CC; i += 256) {
        s->pa[i] = softplusf(alpha[i]);
        s->pd[i] = softplusf(delta[i]) + EPSF;
    }
    if (tid < CC) s->spmu[tid] = softplusf(mu[tid]);
    if (tid < KK) { s->ex[tid] = cf[tid]; s->ftc_s[tid] = ftc[tid]; }
    __syncthreads();

    // ---- phase 2: event bitmasks via ballot (16 windows, 8 warps x 2) ----
    for (int r = 0; r < 2; r++) {
        int w = wrp + 8 * r;
        int evv = s->ev[w * 32 + lane];
        unsigned mym = 0u;
#pragma unroll
        for (int e = 0; e < CC; e++) {
            unsigned m = __ballot_sync(0xffffffffu, evv == e);
            if (lane == e) mym = m;
        }
        s->mask[w * CC + lane] = mym;
    }
    __syncthreads();

    // ---- phase 3a: warp0 = word-prefix + group-base scans; warp1 = cf max+exp ----
    if (wrp == 0) {
        int c = 0;
#pragma unroll
        for (int w = 0; w < NW; w++) {
            s->wpref[w * CC + lane] = c;
            c += __popc(s->mask[w * CC + lane]);
        }
        s->wpref[NW * CC + lane] = c;      // total n
        s->mask [NW * CC + lane] = 0u;     // pad word for J=512
        s->gn[lane] = c;
        int on = c, og = c + 1;            // inclusive scans
#pragma unroll
        for (int d = 1; d < 32; d <<= 1) {
            int v1 = __shfl_up_sync(0xffffffffu, on, d);
            int v2 = __shfl_up_sync(0xffffffffu, og, d);
            if (lane >= d) { on += v1; og += v2; }
        }
        s->obase[lane] = on - c;           // exclusive
        s->gbase[lane] = og - (c + 1);
    } else if (wrp == 1) {
        float a0 = s->ex[lane],      a1 = s->ex[lane + 32];
        float a2 = s->ex[lane + 64], a3 = s->ex[lane + 96];
        float m = fmaxf(fmaxf(a0, a1), fmaxf(a2, a3));
#pragma unroll
        for (int d = 16; d >= 1; d >>= 1)
            m = fmaxf(m, __shfl_xor_sync(0xffffffffu, m, d));
        float v0 = expf(a0 - m), v1 = expf(a1 - m);
        float v2 = expf(a2 - m), v3 = expf(a3 - m);
        __syncwarp();
        s->ex[lane] = v0; s->ex[lane + 32] = v1;
        s->ex[lane + 64] = v2; s->ex[lane + 96] = v3;
    }
    __syncthreads();

    // ---- phase 3b: scatter times into grouped order; den partials (fixed order) ----
    for (int t = tid; t < TT; t += 256) {
        int e = s->ev[t];
        int w = t >> 5, rb = t & 31;
        int j = s->wpref[w * CC + e]
              + __popc(s->mask[w * CC + e] & ((1u << rb) - 1u));
        s->gtg[s->obase[e] + j] = s->t[t];
    }
    if (wrp < 4) {   // warp q sums quarter q of k-space per c-lane, ascending k
        float d = 0.f;
#pragma unroll
        for (int kk = 0; kk < 32; kk++) {
            int k = wrp * 32 + kk;
            if (s->ftc_s[k] == lane) d += s->ex[k];
        }
        s->part[wrp * CC + lane] = d;
    }
    __syncthreads();

    // ---- phase 4: fine probs; GP prefix build (warp wrp -> groups wrp+8q) ----
    if (tid < KK) {
        int c = s->ftc_s[tid];
        float den = ((s->part[c] + s->part[CC + c]) + s->part[2 * CC + c])
                  + s->part[3 * CC + c];
        s->pf[tid] = s->ex[tid] / den;
    }
#pragma unroll
    for (int q = 0; q < 4; q++) {
        const int e  = wrp + 8 * q;
        const float pdv = s->pd[e * CC + lane];
        const float pav = s->pa[e * CC + lane];
        const int n  = s->gn[e];
        const int ob = s->obase[e];
        float* g = &s->gp[s->gbase[e] * CC];
        g[lane] = 0.f;                       // j = 0 row
        float acc = 0.f;
        int j = 0;
        for (; j + 4 <= n; j += 4) {         // pipeline 4 exps ahead of FADD chain
            float x0 = __expf(pdv * s->gtg[ob + j]);
            float x1 = __expf(pdv * s->gtg[ob + j + 1]);
            float x2 = __expf(pdv * s->gtg[ob + j + 2]);
            float x3 = __expf(pdv * s->gtg[ob + j + 3]);
            acc += x0; g[(j + 1) * CC + lane] = acc * pav;
            acc += x1; g[(j + 2) * CC + lane] = acc * pav;
            acc += x2; g[(j + 3) * CC + lane] = acc * pav;
            acc += x3; g[(j + 4) * CC + lane] = acc * pav;
        }
        for (; j < n; j++) {
            acc += __expf(pdv * s->gtg[ob + j]);
            g[(j + 1) * CC + lane] = acc * pav;
        }
    }
    __syncthreads();

    // ---- phase 5: main evaluation. warp handles 4 tp's; lane = c ----
    const int tp0 = (blockIdx.x * 8 + wrp) * 4;
    float tt[4], ntt[4];
#pragma unroll
    for (int i = 0; i < 4; i++) {
        tt[i]  = time_tensor[b * TP + tp0 + i];
        ntt[i] = -tt[i];
    }

    // branchless binary count: J = #events with (tt - pt) > EPS (warp-uniform)
    int pos[4] = {0, 0, 0, 0};
#pragma unroll
    for (int st = 512; st >= 1; st >>= 1) {
#pragma unroll
        for (int i = 0; i < 4; i++) {
            int cand = pos[i] + st;
            if (cand <= TT && (tt[i] - s->t[cand - 1] > EPSF)) pos[i] = cand;
        }
    }

    // lane l resolves GP row for event-type e = l via bitmask popcount
    int rowl[4];
#pragma unroll
    for (int i = 0; i < 4; i++) {
        int J = pos[i], wd = J >> 5, rb = J & 31;
        int jl = s->wpref[wd * CC + lane]
               + __popc(s->mask[wd * CC + lane] & ((1u << rb) - 1u));
        rowl[i] = s->gbase[lane] + jl;
    }

    float acc[4] = {0.f, 0.f, 0.f, 0.f};
#pragma unroll
    for (int e = 0; e < CC; e++) {
        float pdv = s->pd[e * CC + lane];
#pragma unroll
        for (int i = 0; i < 4; i++) {
            int r = __shfl_sync(0xffffffffu, rowl[i], e);
            float gpv = s->gp[r * CC + lane];           // conflict-free LDS
            acc[i] = fmaf(__expf(pdv * ntt[i]), gpv, acc[i]);
        }
    }

    // epilogue tables + scatter: out[k] = (acc[ftc[k]] + spmu[c]) * pfine[k]
    int ck[4]; float pfv[4], smv[4];
#pragma unroll
    for (int j = 0; j < 4; j++) {
        int k = lane + 32 * j;
        ck[j]  = s->ftc_s[k];
        pfv[j] = s->pf[k];
        smv[j] = s->spmu[ck[j]];
    }
#pragma unroll
    for (int i = 0; i < 4; i++) {
        float* o = out + (b * TP + tp0 + i) * KK;
#pragma unroll
        for (int j = 0; j < 4; j++) {
            float v = __shfl_sync(0xffffffffu, acc[i], ck[j]);
            o[lane + 32 * j] = (v + smv[j]) * pfv[j];
        }
    }
}

// ---------------- launch ----------------
extern "C" void kernel_launch(void* const* d_in, const int* in_sizes, int n_in,
                              void* d_out, int out_size)
{
    const int*   past_event  = (const int*)  d_in[0];
    const float* past_time   = (const float*)d_in[1];
    const float* time_tensor = (const float*)d_in[2];
    const float* mu          = (const float*)d_in[3];
    const float* alpha       = (const float*)d_in[4];
    const float* delta       = (const float*)d_in[5];
    const float* cf_logits   = (const float*)d_in[6];
    const int*   ftc         = (const int*)  d_in[7];
    float* out = (float*)d_out;

    static_assert(sizeof(Smem) < 200 * 1024, "smem too large");
    cudaFuncSetAttribute(fused_kernel,
                         cudaFuncAttributeMaxDynamicSharedMemorySize,
                         (int)sizeof(Smem));
    fused_kernel<<<dim3(TP / 32, BB), 256, sizeof(Smem)>>>(
        past_event, past_time, time_tensor, mu, alpha, delta, cf_logits, ftc, out);
}

// round 10
// speedup vs baseline: 2.7224x; 1.1970x over previous
#include <cuda_runtime.h>
#include <cuda_bf16.h>
#include <math.h>

// Problem constants (fixed by the reference)
#define BB 4
#define TT 512
#define TP 1024
#define CC 32
#define KK 128
#define NW 16                 // 32-bit words per 512-event mask
#define GPROWS (TT + CC)      // 544 GP rows per batch
#define NTHREADS 512
#define EPSF 2.220446049250313e-16f

struct Smem {
    float    gp[GPROWS * CC];        // 68 KB: pa[e][c]*prefix-sum exp(pd*pt)
    float    pd[CC * CC];            // softplus(delta)[e][c]+EPS
    float    pa[CC * CC];            // softplus(alpha)[e][c]
    float    t[TT];                  // batch's sorted event times
    float    gtg[TT];                // times grouped by event type
    int      ev[TT];                 // event ids
    unsigned mask[(NW + 1) * CC];    // [w][e] bitmask (word 16 = 0 pad)
    int      wpref[(NW + 1) * CC];   // [w][e] count below word w (word 16 = n)
    int      obase[CC];              // group start in gtg
    int      gbase[CC];              // group start row in gp
    int      gn[CC];                 // group sizes
    float    ex[KK];                 // cf logits -> exp(cf - max)
    int      ftc_s[KK];
    float    part[4 * CC];           // den partials (quarters, fixed order)
    float    pf[KK];                 // fine probs
    float    spmu[CC];               // softplus(mu)
};

// fast softplus: abs err ~1e-6; amplified by pt<=25.6 in exponent -> <=2.5e-5 rel (ok vs 1e-3)
__device__ __forceinline__ float softplusf(float x) {
    return __logf(1.0f + __expf(x));
}

extern __shared__ char smem_raw[];

// One fused kernel: block = (tp-chunk, batch). Each block rebuilds its batch's
// setup in shared (redundant, parallel), then evaluates 32 tp's (2 per warp).
__global__ __launch_bounds__(NTHREADS, 1) void fused_kernel(
    const int*   __restrict__ past_event,   // [B,T]
    const float* __restrict__ past_time,    // [B,T]
    const float* __restrict__ time_tensor,  // [B,TP]
    const float* __restrict__ mu,           // [C]
    const float* __restrict__ alpha,        // [C,C]
    const float* __restrict__ delta,        // [C,C]
    const float* __restrict__ cf,           // [K]
    const int*   __restrict__ ftc,          // [K]
    float*       __restrict__ out)          // [B,TP,K]
{
    Smem* s = reinterpret_cast<Smem*>(smem_raw);
    const int b    = blockIdx.y;
    const int tid  = threadIdx.x;
    const int lane = tid & 31;
    const int wrp  = tid >> 5;               // 0..15

    // ---- phase 1: global loads + softplus tables ----
    if (tid < TT) {
        s->ev[tid] = past_event[b * TT + tid];
        s->t[tid]  = past_time [b * TT + tid];
    }
    for (int i = tid; i < CC * CC; i += NTHREADS) {
        s->pa[i] = softplusf(alpha[i]);
        s->pd[i] = softplusf(delta[i]) + EPSF;
    }
    if (tid < CC) s->spmu[tid] = softplusf(mu[tid]);
    if (tid < KK) { s->ex[tid] = cf[tid]; s->ftc_s[tid] = ftc[tid]; }
    __syncthreads();

    // ---- phase 2: event bitmasks via ballot (16 windows, 16 warps -> 1 round) ----
    {
        int evv = s->ev[wrp * 32 + lane];
        unsigned mym = 0u;
#pragma unroll
        for (int e = 0; e < CC; e++) {
            unsigned m = __ballot_sync(0xffffffffu, evv == e);
            if (lane == e) mym = m;
        }
        s->mask[wrp * CC + lane] = mym;
    }
    __syncthreads();

    // ---- phase 3a: warp0 = word-prefix + group-base scans; warp1 = cf max+exp ----
    if (wrp == 0) {
        int c = 0;
#pragma unroll
        for (int w = 0; w < NW; w++) {
            s->wpref[w * CC + lane] = c;
            c += __popc(s->mask[w * CC + lane]);
        }
        s->wpref[NW * CC + lane] = c;      // total n
        s->mask [NW * CC + lane] = 0u;     // pad word for J=512
        s->gn[lane] = c;
        int on = c, og = c + 1;            // inclusive scans
#pragma unroll
        for (int d = 1; d < 32; d <<= 1) {
            int v1 = __shfl_up_sync(0xffffffffu, on, d);
            int v2 = __shfl_up_sync(0xffffffffu, og, d);
            if (lane >= d) { on += v1; og += v2; }
        }
        s->obase[lane] = on - c;           // exclusive
        s->gbase[lane] = og - (c + 1);
    } else if (wrp == 1) {
        float a0 = s->ex[lane],      a1 = s->ex[lane + 32];
        float a2 = s->ex[lane + 64], a3 = s->ex[lane + 96];
        float m = fmaxf(fmaxf(a0, a1), fmaxf(a2, a3));
#pragma unroll
        for (int d = 16; d >= 1; d >>= 1)
            m = fmaxf(m, __shfl_xor_sync(0xffffffffu, m, d));
        float v0 = __expf(a0 - m), v1 = __expf(a1 - m);
        float v2 = __expf(a2 - m), v3 = __expf(a3 - m);
        __syncwarp();
        s->ex[lane] = v0; s->ex[lane + 32] = v1;
        s->ex[lane + 64] = v2; s->ex[lane + 96] = v3;
    }
    __syncthreads();

    // ---- phase 3b: scatter times into grouped order; den partials (fixed order) ----
    if (tid < TT) {
        int t = tid;
        int e = s->ev[t];
        int w = t >> 5, rb = t & 31;
        int j = s->wpref[w * CC + e]
              + __popc(s->mask[w * CC + e] & ((1u << rb) - 1u));
        s->gtg[s->obase[e] + j] = s->t[t];
    }
    if (wrp < 4) {   // warp q sums quarter q of k-space per c-lane, ascending k
        float d = 0.f;
#pragma unroll
        for (int kk = 0; kk < 32; kk++) {
            int k = wrp * 32 + kk;
            if (s->ftc_s[k] == lane) d += s->ex[k];
        }
        s->part[wrp * CC + lane] = d;
    }
    __syncthreads();

    // ---- phase 4: fine probs; GP prefix build (warp wrp -> groups wrp, wrp+16) ----
    if (tid < KK) {
        int c = s->ftc_s[tid];
        float den = ((s->part[c] + s->part[CC + c]) + s->part[2 * CC + c])
                  + s->part[3 * CC + c];
        s->pf[tid] = s->ex[tid] / den;
    }
#pragma unroll
    for (int q = 0; q < 2; q++) {
        const int e  = wrp + 16 * q;
        const float pdv = s->pd[e * CC + lane];
        const float pav = s->pa[e * CC + lane];
        const int n  = s->gn[e];
        const int ob = s->obase[e];
        float* g = &s->gp[s->gbase[e] * CC];
        g[lane] = 0.f;                       // j = 0 row
        float acc = 0.f;
        int j = 0;
        for (; j + 4 <= n; j += 4) {         // pipeline 4 exps ahead of FADD chain
            float x0 = __expf(pdv * s->gtg[ob + j]);
            float x1 = __expf(pdv * s->gtg[ob + j + 1]);
            float x2 = __expf(pdv * s->gtg[ob + j + 2]);
            float x3 = __expf(pdv * s->gtg[ob + j + 3]);
            acc += x0; g[(j + 1) * CC + lane] = acc * pav;
            acc += x1; g[(j + 2) * CC + lane] = acc * pav;
            acc += x2; g[(j + 3) * CC + lane] = acc * pav;
            acc += x3; g[(j + 4) * CC + lane] = acc * pav;
        }
        for (; j < n; j++) {
            acc += __expf(pdv * s->gtg[ob + j]);
            g[(j + 1) * CC + lane] = acc * pav;
        }
    }
    __syncthreads();

    // ---- phase 5: main evaluation. warp handles 2 tp's; lane = c ----
    const int tp0 = (blockIdx.x * 16 + wrp) * 2;
    float tt[2], ntt[2];
#pragma unroll
    for (int i = 0; i < 2; i++) {
        tt[i]  = time_tensor[b * TP + tp0 + i];
        ntt[i] = -tt[i];
    }

    // branchless binary count: J = #events with (tt - pt) > EPS (warp-uniform)
    int pos[2] = {0, 0};
#pragma unroll
    for (int st = 512; st >= 1; st >>= 1) {
#pragma unroll
        for (int i = 0; i < 2; i++) {
            int cand = pos[i] + st;
            if (cand <= TT && (tt[i] - s->t[cand - 1] > EPSF)) pos[i] = cand;
        }
    }

    // lane l resolves GP row for event-type e = l via bitmask popcount
    int rowl[2];
#pragma unroll
    for (int i = 0; i < 2; i++) {
        int J = pos[i], wd = J >> 5, rb = J & 31;
        int jl = s->wpref[wd * CC + lane]
               + __popc(s->mask[wd * CC + lane] & ((1u << rb) - 1u));
        rowl[i] = s->gbase[lane] + jl;
    }

    float acc[2] = {0.f, 0.f};
#pragma unroll
    for (int e = 0; e < CC; e++) {
        float pdv = s->pd[e * CC + lane];
#pragma unroll
        for (int i = 0; i < 2; i++) {
            int r = __shfl_sync(0xffffffffu, rowl[i], e);
            float gpv = s->gp[r * CC + lane];           // conflict-free LDS
            acc[i] = fmaf(__expf(pdv * ntt[i]), gpv, acc[i]);
        }
    }

    // epilogue tables + scatter: out[k] = (acc[ftc[k]] + spmu[c]) * pfine[k]
    int ck[4]; float pfv[4], smv[4];
#pragma unroll
    for (int j = 0; j < 4; j++) {
        int k = lane + 32 * j;
        ck[j]  = s->ftc_s[k];
        pfv[j] = s->pf[k];
        smv[j] = s->spmu[ck[j]];
    }
#pragma unroll
    for (int i = 0; i < 2; i++) {
        float* o = out + (b * TP + tp0 + i) * KK;
#pragma unroll
        for (int j = 0; j < 4; j++) {
            float v = __shfl_sync(0xffffffffu, acc[i], ck[j]);
            o[lane + 32 * j] = (v + smv[j]) * pfv[j];
        }
    }
}

// ---------------- launch ----------------
extern "C" void kernel_launch(void* const* d_in, const int* in_sizes, int n_in,
                              void* d_out, int out_size)
{
    const int*   past_event  = (const int*)  d_in[0];
    const float* past_time   = (const float*)d_in[1];
    const float* time_tensor = (const float*)d_in[2];
    const float* mu          = (const float*)d_in[3];
    const float* alpha       = (const float*)d_in[4];
    const float* delta       = (const float*)d_in[5];
    const float* cf_logits   = (const float*)d_in[6];
    const int*   ftc         = (const int*)  d_in[7];
    float* out = (float*)d_out;

    static_assert(sizeof(Smem) < 200 * 1024, "smem too large");
    cudaFuncSetAttribute(fused_kernel,
                         cudaFuncAttributeMaxDynamicSharedMemorySize,
                         (int)sizeof(Smem));
    fused_kernel<<<dim3(TP / 32, BB), NTHREADS, sizeof(Smem)>>>(
        past_event, past_time, time_tensor, mu, alpha, delta, cf_logits, ftc, out);
}